// round 3
// baseline (speedup 1.0000x reference)
#include <cuda_runtime.h>
#include <cuda_bf16.h>
#include <math.h>

// Problem constants
#define B_   4
#define LV   2048
#define LE   64
#define LJ   2112     // Lv + Le
#define D_   960
#define H_   15
#define KVH_ 5
#define HD_  64
#define GQA  3        // H / KVH

// Scratch (device globals: no allocation allowed)
__device__ __align__(16) float g_xn  [B_ * LJ * D_];          // normalized hidden, joint layout
__device__ __align__(16) float g_q   [B_ * LJ * H_  * HD_];   // q, joint
__device__ __align__(16) float g_k   [B_ * LJ * KVH_* HD_];   // k, joint
__device__ __align__(16) float g_v   [B_ * LJ * KVH_* HD_];   // v, joint
__device__ __align__(16) float g_attn[B_ * LJ * H_  * HD_];   // attention out, joint

// -------------------------------------------------------------------------
// RMSNorm: one block per token row. Writes into joint layout at (b*LJ+offset+r).
// -------------------------------------------------------------------------
__global__ void rmsnorm_kernel(const float* __restrict__ h, const float* __restrict__ w,
                               float* __restrict__ out, int Lseg, int offset)
{
    int m = blockIdx.x;
    int b = m / Lseg, r = m % Lseg;
    const float* x = h + (size_t)m * D_;
    float* y = out + ((size_t)(b * LJ + offset + r)) * D_;

    float ss = 0.f;
    for (int i = threadIdx.x; i < D_; i += blockDim.x) { float t = x[i]; ss += t * t; }

    __shared__ float red[32];
    for (int o = 16; o; o >>= 1) ss += __shfl_down_sync(0xffffffffu, ss, o);
    if ((threadIdx.x & 31) == 0) red[threadIdx.x >> 5] = ss;
    __syncthreads();
    if (threadIdx.x < 32) {
        float v2 = (threadIdx.x < (blockDim.x >> 5)) ? red[threadIdx.x] : 0.f;
        for (int o = 16; o; o >>= 1) v2 += __shfl_down_sync(0xffffffffu, v2, o);
        if (threadIdx.x == 0) red[0] = rsqrtf(v2 / (float)D_ + 1e-6f);
    }
    __syncthreads();
    float rs = red[0];
    for (int i = threadIdx.x; i < D_; i += blockDim.x) y[i] = x[i] * rs * w[i];
}

// -------------------------------------------------------------------------
// Generic tiled fp32 GEMM with joint row-mapping on A & C and optional residual.
//   C[map(m), n] = sum_k A[map(m), k] * W[k, n]  (+ residual[m, n])
//   map(m) = (m / Lseg) * LJ + offset + (m % Lseg)
// Tile: 128x64x16, 256 threads, 8x4 per thread.
// -------------------------------------------------------------------------
__global__ __launch_bounds__(256)
void gemm_kernel(const float* __restrict__ A, const float* __restrict__ W,
                 float* __restrict__ C,
                 int M, int N, int K,
                 int Lseg, int offset,
                 int lda, int ldw, int ldc,
                 const float* __restrict__ residual, int ldres)
{
    const int BM = 128, BN = 64, BK = 16;
    __shared__ float As[BK][BM];   // transposed store: As[k][m]
    __shared__ float Bs[BK][BN];

    int tid = threadIdx.x;
    int tx = tid & 15;        // 0..15 -> 4 cols each
    int ty = tid >> 4;        // 0..15 -> 8 rows each
    int row0 = blockIdx.x * BM;
    int col0 = blockIdx.y * BN;

    float acc[8][4];
    #pragma unroll
    for (int i = 0; i < 8; i++)
        #pragma unroll
        for (int j = 0; j < 4; j++) acc[i][j] = 0.f;

    for (int k0 = 0; k0 < K; k0 += BK) {
        // Load A tile: 128x16 floats = 512 float4, 2 per thread
        #pragma unroll
        for (int i = 0; i < 2; i++) {
            int li = tid + i * 256;       // 0..511
            int r  = li >> 2;             // 0..127
            int c4 = li & 3;              // float4 index into BK
            int gr = row0 + r;
            float4 val = make_float4(0.f, 0.f, 0.f, 0.f);
            if (gr < M) {
                int arow = (gr / Lseg) * LJ + offset + (gr % Lseg);
                val = *(const float4*)(A + (size_t)arow * lda + k0 + c4 * 4);
            }
            As[c4 * 4 + 0][r] = val.x;
            As[c4 * 4 + 1][r] = val.y;
            As[c4 * 4 + 2][r] = val.z;
            As[c4 * 4 + 3][r] = val.w;
        }
        // Load B tile: 16x64 floats = 256 float4, 1 per thread
        {
            int r  = tid >> 4;   // k row
            int c4 = tid & 15;   // col group
            int gc = col0 + c4 * 4;
            float4 val = make_float4(0.f, 0.f, 0.f, 0.f);
            if (gc < N) val = *(const float4*)(W + (size_t)(k0 + r) * ldw + gc);
            *(float4*)&Bs[r][c4 * 4] = val;
        }
        __syncthreads();

        #pragma unroll
        for (int kk = 0; kk < BK; kk++) {
            float4 a0 = *(const float4*)&As[kk][ty * 8 + 0];
            float4 a1 = *(const float4*)&As[kk][ty * 8 + 4];
            float4 bb = *(const float4*)&Bs[kk][tx * 4];
            float a[8] = {a0.x, a0.y, a0.z, a0.w, a1.x, a1.y, a1.z, a1.w};
            float bv[4] = {bb.x, bb.y, bb.z, bb.w};
            #pragma unroll
            for (int i = 0; i < 8; i++)
                #pragma unroll
                for (int j = 0; j < 4; j++) acc[i][j] += a[i] * bv[j];
        }
        __syncthreads();
    }

    #pragma unroll
    for (int i = 0; i < 8; i++) {
        int gr = row0 + ty * 8 + i;
        if (gr >= M) continue;
        int crow = (gr / Lseg) * LJ + offset + (gr % Lseg);
        #pragma unroll
        for (int j = 0; j < 4; j++) {
            int gc = col0 + tx * 4 + j;
            if (gc < N) {
                float val = acc[i][j];
                if (residual) val += residual[(size_t)gr * ldres + gc];
                C[(size_t)crow * ldc + gc] = val;
            }
        }
    }
}

// -------------------------------------------------------------------------
// RoPE in-place on g_q and g_k (joint layout). Each thread: one (token, head, dh) pair.
// -------------------------------------------------------------------------
__global__ void rope_kernel(const int* __restrict__ pos_v, const int* __restrict__ pos_e)
{
    const int total = B_ * LJ * (H_ + KVH_) * (HD_ / 2);
    int idx = blockIdx.x * blockDim.x + threadIdx.x;
    if (idx >= total) return;
    int dh   = idx & 31;
    int t    = idx >> 5;
    int head = t % (H_ + KVH_);
    int tok  = t / (H_ + KVH_);
    int b = tok / LJ, i = tok % LJ;

    int p = (i < LV) ? pos_v[b * LV + i] : pos_e[b * LE + (i - LV)];
    float ts  = powf(10000.0f, (float)dh * (2.0f / 64.0f));
    float rad = (float)p / ts;
    float sn, cs;
    sincosf(rad, &sn, &cs);

    float* base;
    if (head < H_) base = g_q + (((size_t)(b * LJ + i)) * H_   + head)        * HD_;
    else           base = g_k + (((size_t)(b * LJ + i)) * KVH_ + (head - H_)) * HD_;

    float x1 = base[dh], x2 = base[dh + 32];
    base[dh]      = x1 * cs - x2 * sn;
    base[dh + 32] = x2 * cs + x1 * sn;
}

// -------------------------------------------------------------------------
// Flash-style attention, 2 threads per query (32 dims each).
// grid = (ceil(LJ/128), B*H), 256 threads. Thread t: query q0 + (t>>1),
// dim half = (t&1)*32. Half dot-products combined via shfl_xor(1).
// Key bound per query: qi < LV -> LV keys; qi >= LV -> qi+1 keys.
// Tiles with k0+32 <= kend_min (kend_min = min over block) take a mask-free
// fast path — all tiles for VLM blocks.
// -------------------------------------------------------------------------
__global__ __launch_bounds__(256)
void attn_kernel()
{
    __shared__ float Ks[32][64];
    __shared__ float Vs[32][64];

    int tid  = threadIdx.x;
    int qloc = tid >> 1;          // 0..127
    int half = tid & 1;           // 0 or 1
    int doff = half * 32;
    int q0   = blockIdx.x * 128;
    int bh   = blockIdx.y;
    int b    = bh / H_, h = bh % H_;
    int kvh  = h / GQA;
    int qi   = q0 + qloc;
    bool active = qi < LJ;

    float qreg[32];
    int kend = 0;
    if (active) {
        const float* qp = g_q + (((size_t)(b * LJ + qi)) * H_ + h) * HD_ + doff;
        #pragma unroll
        for (int d = 0; d < 32; d++) qreg[d] = qp[d] * 0.125f;   // HD^-0.5
        kend = (qi < LV) ? LV : (qi + 1);
    }
    // Max keys needed by any query in this block, and min fully-valid bound
    int kend_blk = (q0 + 127 < LV) ? LV : min(LJ, q0 + 128);
    int kend_min = (q0 < LV) ? LV : (q0 + 1);

    float m = -3.0e38f, l = 0.f;
    float acc[32];
    #pragma unroll
    for (int d = 0; d < 32; d++) acc[d] = 0.f;

    for (int k0 = 0; k0 < kend_blk; k0 += 32) {
        int nk = min(32, kend_blk - k0);
        __syncthreads();
        // Load K,V tiles: 32x64 floats each = 512 float4 each; 2 per thread each
        #pragma unroll
        for (int i = 0; i < 2; i++) {
            int li = tid + i * 256;   // 0..511
            int r  = li >> 4;         // 0..31
            int c4 = li & 15;
            float4 k4 = make_float4(0.f, 0.f, 0.f, 0.f);
            float4 v4 = make_float4(0.f, 0.f, 0.f, 0.f);
            if (r < nk) {
                size_t off = (((size_t)(b * LJ + k0 + r)) * KVH_ + kvh) * HD_ + c4 * 4;
                k4 = *(const float4*)(g_k + off);
                v4 = *(const float4*)(g_v + off);
            }
            *(float4*)&Ks[r][c4 * 4] = k4;
            *(float4*)&Vs[r][c4 * 4] = v4;
        }
        __syncthreads();

        bool full = (k0 + 32 <= kend_min);   // no masking needed for any active query

        // Half dot-products + pair combine
        float s[32];
        if (full) {
            #pragma unroll 4
            for (int j = 0; j < 32; j++) {
                const float4* kr = (const float4*)&Ks[j][doff];
                float dot = 0.f;
                #pragma unroll
                for (int d4 = 0; d4 < 8; d4++) {
                    float4 kk = kr[d4];
                    dot += qreg[d4 * 4 + 0] * kk.x + qreg[d4 * 4 + 1] * kk.y
                         + qreg[d4 * 4 + 2] * kk.z + qreg[d4 * 4 + 3] * kk.w;
                }
                dot += __shfl_xor_sync(0xffffffffu, dot, 1);
                s[j] = dot;
            }
        } else {
            #pragma unroll 4
            for (int j = 0; j < 32; j++) {
                const float4* kr = (const float4*)&Ks[j][doff];
                float dot = 0.f;
                #pragma unroll
                for (int d4 = 0; d4 < 8; d4++) {
                    float4 kk = kr[d4];
                    dot += qreg[d4 * 4 + 0] * kk.x + qreg[d4 * 4 + 1] * kk.y
                         + qreg[d4 * 4 + 2] * kk.z + qreg[d4 * 4 + 3] * kk.w;
                }
                dot += __shfl_xor_sync(0xffffffffu, dot, 1);
                int jj = k0 + j;
                s[j] = (active && jj < kend) ? dot : -3.0e38f;
            }
        }

        float mt = -3.0e38f;
        #pragma unroll
        for (int j = 0; j < 32; j++) mt = fmaxf(mt, s[j]);
        if (mt > -2.0e38f) {                    // at least one valid key in tile
            float mnew = fmaxf(m, mt);
            float corr = __expf(m - mnew);
            l *= corr;
            #pragma unroll
            for (int d = 0; d < 32; d++) acc[d] *= corr;

            #pragma unroll 2
            for (int j = 0; j < 32; j++) {
                float p = __expf(s[j] - mnew);
                l += p;
                const float4* vr = (const float4*)&Vs[j][doff];
                #pragma unroll
                for (int d4 = 0; d4 < 8; d4++) {
                    float4 vv = vr[d4];
                    acc[d4 * 4 + 0] += p * vv.x;
                    acc[d4 * 4 + 1] += p * vv.y;
                    acc[d4 * 4 + 2] += p * vv.z;
                    acc[d4 * 4 + 3] += p * vv.w;
                }
            }
            m = mnew;
        }
    }

    if (active) {
        float inv = 1.f / l;
        float* op = g_attn + ((size_t)(b * LJ + qi)) * (H_ * HD_) + h * HD_ + doff;
        #pragma unroll
        for (int d = 0; d < 32; d++) op[d] = acc[d] * inv;
    }
}

// -------------------------------------------------------------------------
// Launch
// -------------------------------------------------------------------------
extern "C" void kernel_launch(void* const* d_in, const int* in_sizes, int n_in,
                              void* d_out, int out_size)
{
    const float* h_v  = (const float*)d_in[0];
    const float* h_e  = (const float*)d_in[1];
    const float* ln_v = (const float*)d_in[2];
    const float* wq_v = (const float*)d_in[3];
    const float* wk_v = (const float*)d_in[4];
    const float* wv_v = (const float*)d_in[5];
    const float* wo_v = (const float*)d_in[6];
    const float* ln_e = (const float*)d_in[7];
    const float* wq_e = (const float*)d_in[8];
    const float* wk_e = (const float*)d_in[9];
    const float* wv_e = (const float*)d_in[10];
    const float* wo_e = (const float*)d_in[11];
    const int*  pos_v = (const int*)d_in[12];
    const int*  pos_e = (const int*)d_in[13];
    float* out = (float*)d_out;

    float *xn, *q, *k, *v, *attn;
    cudaGetSymbolAddress((void**)&xn,   g_xn);
    cudaGetSymbolAddress((void**)&q,    g_q);
    cudaGetSymbolAddress((void**)&k,    g_k);
    cudaGetSymbolAddress((void**)&v,    g_v);
    cudaGetSymbolAddress((void**)&attn, g_attn);

    // 1) RMSNorm into joint-layout xn
    rmsnorm_kernel<<<B_ * LV, 256>>>(h_v, ln_v, xn, LV, 0);
    rmsnorm_kernel<<<B_ * LE, 256>>>(h_e, ln_e, xn, LE, LV);

    // 2) QKV GEMMs (per stream), writing into joint q/k/v
    const int Mv = B_ * LV, Me = B_ * LE;
    dim3 gqv((Mv + 127) / 128, (960 + 63) / 64);
    dim3 gkv((Mv + 127) / 128, (320 + 63) / 64);
    dim3 gqe((Me + 127) / 128, (960 + 63) / 64);
    dim3 gke((Me + 127) / 128, (320 + 63) / 64);
    gemm_kernel<<<gqv, 256>>>(xn, wq_v, q, Mv, 960, 960, LV, 0, D_, 960, 960, nullptr, 0);
    gemm_kernel<<<gkv, 256>>>(xn, wk_v, k, Mv, 320, 960, LV, 0, D_, 320, 320, nullptr, 0);
    gemm_kernel<<<gkv, 256>>>(xn, wv_v, v, Mv, 320, 960, LV, 0, D_, 320, 320, nullptr, 0);
    gemm_kernel<<<gqe, 256>>>(xn, wq_e, q, Me, 960, 960, LE, LV, D_, 960, 960, nullptr, 0);
    gemm_kernel<<<gke, 256>>>(xn, wk_e, k, Me, 320, 960, LE, LV, D_, 320, 320, nullptr, 0);
    gemm_kernel<<<gke, 256>>>(xn, wv_e, v, Me, 320, 960, LE, LV, D_, 320, 320, nullptr, 0);

    // 3) RoPE in-place on q, k
    {
        const int total = B_ * LJ * (H_ + KVH_) * (HD_ / 2);
        rope_kernel<<<(total + 255) / 256, 256>>>(pos_v, pos_e);
    }

    // 4) Attention
    {
        dim3 grid((LJ + 127) / 128, B_ * H_);
        attn_kernel<<<grid, 256>>>();
    }

    // 5) Output projection + residual, into d_out (joint layout == concat on axis 1)
    gemm_kernel<<<gqv, 256>>>(attn, wo_v, out, Mv, 960, 960, LV, 0, 960, 960, 960, h_v, 960);
    gemm_kernel<<<gqe, 256>>>(attn, wo_e, out, Me, 960, 960, LE, LV, 960, 960, 960, h_e, 960);
}

// round 4
// speedup vs baseline: 4.6482x; 4.6482x over previous
#include <cuda_runtime.h>
#include <cuda_bf16.h>
#include <math.h>
#include <stdint.h>

// Problem constants
#define B_   4
#define LV   2048
#define LE   64
#define LJ   2112     // Lv + Le
#define D_   960
#define H_   15
#define KVH_ 5
#define HD_  64
#define GQA  3        // H / KVH

// Scratch (device globals: no allocation allowed)
__device__ __align__(16) float g_xn  [B_ * LJ * D_];
__device__ __align__(16) float g_q   [B_ * LJ * H_  * HD_];
__device__ __align__(16) float g_k   [B_ * LJ * KVH_* HD_];
__device__ __align__(16) float g_v   [B_ * LJ * KVH_* HD_];
__device__ __align__(16) float g_attn[B_ * LJ * H_  * HD_];

// -------------------------------------------------------------------------
// tf32 helpers
// -------------------------------------------------------------------------
__device__ __forceinline__ uint32_t f2tf(float f) {
    uint32_t u;
    asm("cvt.rna.tf32.f32 %0, %1;" : "=r"(u) : "f"(f));
    return u;
}

// D(16x8) += A(16x8,row) * B(8x8,col); fp32 accum
__device__ __forceinline__ void mma_tf32(float d[4], const uint32_t a[4], const uint32_t b[2]) {
    asm volatile(
        "mma.sync.aligned.m16n8k8.row.col.f32.tf32.tf32.f32 "
        "{%0,%1,%2,%3}, {%4,%5,%6,%7}, {%8,%9}, {%0,%1,%2,%3};"
        : "+f"(d[0]), "+f"(d[1]), "+f"(d[2]), "+f"(d[3])
        : "r"(a[0]), "r"(a[1]), "r"(a[2]), "r"(a[3]), "r"(b[0]), "r"(b[1]));
}

// -------------------------------------------------------------------------
// RMSNorm (unchanged)
// -------------------------------------------------------------------------
__global__ void rmsnorm_kernel(const float* __restrict__ h, const float* __restrict__ w,
                               float* __restrict__ out, int Lseg, int offset)
{
    int m = blockIdx.x;
    int b = m / Lseg, r = m % Lseg;
    const float* x = h + (size_t)m * D_;
    float* y = out + ((size_t)(b * LJ + offset + r)) * D_;

    float ss = 0.f;
    for (int i = threadIdx.x; i < D_; i += blockDim.x) { float t = x[i]; ss += t * t; }

    __shared__ float red[32];
    for (int o = 16; o; o >>= 1) ss += __shfl_down_sync(0xffffffffu, ss, o);
    if ((threadIdx.x & 31) == 0) red[threadIdx.x >> 5] = ss;
    __syncthreads();
    if (threadIdx.x < 32) {
        float v2 = (threadIdx.x < (blockDim.x >> 5)) ? red[threadIdx.x] : 0.f;
        for (int o = 16; o; o >>= 1) v2 += __shfl_down_sync(0xffffffffu, v2, o);
        if (threadIdx.x == 0) red[0] = rsqrtf(v2 / (float)D_ + 1e-6f);
    }
    __syncthreads();
    float rs = red[0];
    for (int i = threadIdx.x; i < D_; i += blockDim.x) y[i] = x[i] * rs * w[i];
}

// -------------------------------------------------------------------------
// tf32 tensor-core GEMM. C[map(m), n] = A[map(m), :] * W[:, n] (+residual[m,n])
// Tiles: BM=128, BN=64, BK=32. 256 threads = 8 warps (4M x 2N), warp does
// 32x32 = 2x4 m16n8k8 tiles. All problem shapes divide tiles exactly.
// Smem pads: As row stride 36 words -> fragment LDS bank = (4r+c)%32 (bijective);
// Bs row stride 72 -> bank = (8k+n)%32 (bijective). Conflict-free.
// -------------------------------------------------------------------------
__global__ __launch_bounds__(256)
void gemm_tc(const float* __restrict__ A, const float* __restrict__ W,
             float* __restrict__ C,
             int Lseg, int offset, int lda, int ldw, int ldc,
             const float* __restrict__ residual, int ldres, int K)
{
    __shared__ uint32_t As[128 * 36];
    __shared__ uint32_t Bs[32 * 72];

    int tid = threadIdx.x;
    int lane = tid & 31, wid = tid >> 5;
    int wm = wid & 3;          // 0..3 -> 32-row slab
    int wn = wid >> 2;         // 0..1 -> 32-col slab
    int lr = lane >> 2, lc = lane & 3;
    int row0 = blockIdx.x * 128;
    int col0 = blockIdx.y * 64;

    float acc[2][4][4];
    #pragma unroll
    for (int mt = 0; mt < 2; mt++)
        #pragma unroll
        for (int nt = 0; nt < 4; nt++)
            #pragma unroll
            for (int i = 0; i < 4; i++) acc[mt][nt][i] = 0.f;

    for (int k0 = 0; k0 < K; k0 += 32) {
        // A tile 128x32: 1024 float4, 4 per thread
        #pragma unroll
        for (int i = 0; i < 4; i++) {
            int li = tid + i * 256;
            int r = li >> 3, c4 = li & 7;
            int gr = row0 + r;
            int arow = (gr / Lseg) * LJ + offset + (gr % Lseg);
            float4 v = *(const float4*)(A + (size_t)arow * lda + k0 + c4 * 4);
            uint32_t* s = &As[r * 36 + c4 * 4];
            s[0] = f2tf(v.x); s[1] = f2tf(v.y); s[2] = f2tf(v.z); s[3] = f2tf(v.w);
        }
        // B tile 32x64: 512 float4, 2 per thread
        #pragma unroll
        for (int i = 0; i < 2; i++) {
            int li = tid + i * 256;
            int r = li >> 4, c4 = li & 15;
            float4 v = *(const float4*)(W + (size_t)(k0 + r) * ldw + col0 + c4 * 4);
            uint32_t* s = &Bs[r * 72 + c4 * 4];
            s[0] = f2tf(v.x); s[1] = f2tf(v.y); s[2] = f2tf(v.z); s[3] = f2tf(v.w);
        }
        __syncthreads();

        #pragma unroll
        for (int k8 = 0; k8 < 4; k8++) {
            uint32_t a[2][4], b[4][2];
            #pragma unroll
            for (int mt = 0; mt < 2; mt++) {
                int r = wm * 32 + mt * 16 + lr;
                int c = k8 * 8 + lc;
                a[mt][0] = As[r * 36 + c];
                a[mt][1] = As[(r + 8) * 36 + c];
                a[mt][2] = As[r * 36 + c + 4];
                a[mt][3] = As[(r + 8) * 36 + c + 4];
            }
            #pragma unroll
            for (int nt = 0; nt < 4; nt++) {
                int n = wn * 32 + nt * 8 + lr;
                int kk = k8 * 8 + lc;
                b[nt][0] = Bs[kk * 72 + n];
                b[nt][1] = Bs[(kk + 4) * 72 + n];
            }
            #pragma unroll
            for (int mt = 0; mt < 2; mt++)
                #pragma unroll
                for (int nt = 0; nt < 4; nt++)
                    mma_tf32(acc[mt][nt], a[mt], b[nt]);
        }
        __syncthreads();
    }

    // Epilogue: C-fragment rows r/r+8, cols 2lc/2lc+1 per n-tile
    #pragma unroll
    for (int mt = 0; mt < 2; mt++) {
        int m0 = row0 + wm * 32 + mt * 16 + lr;
        #pragma unroll
        for (int hh = 0; hh < 2; hh++) {
            int gm = m0 + hh * 8;
            int cm = (gm / Lseg) * LJ + offset + (gm % Lseg);
            #pragma unroll
            for (int nt = 0; nt < 4; nt++) {
                int gc = col0 + wn * 32 + nt * 8 + lc * 2;
                float v0 = acc[mt][nt][hh * 2 + 0];
                float v1 = acc[mt][nt][hh * 2 + 1];
                if (residual) {
                    v0 += residual[(size_t)gm * ldres + gc];
                    v1 += residual[(size_t)gm * ldres + gc + 1];
                }
                float2 o; o.x = v0; o.y = v1;
                *(float2*)(C + (size_t)cm * ldc + gc) = o;
            }
        }
    }
}

// -------------------------------------------------------------------------
// RoPE (unchanged)
// -------------------------------------------------------------------------
__global__ void rope_kernel(const int* __restrict__ pos_v, const int* __restrict__ pos_e)
{
    const int total = B_ * LJ * (H_ + KVH_) * (HD_ / 2);
    int idx = blockIdx.x * blockDim.x + threadIdx.x;
    if (idx >= total) return;
    int dh   = idx & 31;
    int t    = idx >> 5;
    int head = t % (H_ + KVH_);
    int tok  = t / (H_ + KVH_);
    int b = tok / LJ, i = tok % LJ;

    int p = (i < LV) ? pos_v[b * LV + i] : pos_e[b * LE + (i - LV)];
    float ts  = powf(10000.0f, (float)dh * (2.0f / 64.0f));
    float rad = (float)p / ts;
    float sn, cs;
    sincosf(rad, &sn, &cs);

    float* base;
    if (head < H_) base = g_q + (((size_t)(b * LJ + i)) * H_   + head)        * HD_;
    else           base = g_k + (((size_t)(b * LJ + i)) * KVH_ + (head - H_)) * HD_;

    float x1 = base[dh], x2 = base[dh + 32];
    base[dh]      = x1 * cs - x2 * sn;
    base[dh + 32] = x2 * cs + x1 * sn;
}

// -------------------------------------------------------------------------
// Tensor-core flash attention. One CTA = one (b,h) x 64 queries.
// 4 warps x 16 query rows. Key tile = 32.
//  S = Q*K^T via m16n8k8 tf32 (Q pre-scaled by HD^-0.5 at smem load)
//  online softmax in C-fragment layout (row group = 4 lanes, shfl_xor 1,2)
//  P -> padded smem (tf32) -> A-fragments -> O += P*V
// VLM blocks (q0 < LV): all tiles full, no masking. Exp block (q0 = LV):
// causal mask in tiles with k0+32 > LV.
// -------------------------------------------------------------------------
__global__ __launch_bounds__(128)
void attn_tc()
{
    __shared__ uint32_t Qs[64 * 68];   // [qrow][dim] pad 68
    __shared__ uint32_t Kt[32 * 68];   // [key][dim]  pad 68
    __shared__ uint32_t Vs[32 * 72];   // [key][dim]  pad 72
    __shared__ uint32_t Ps[64 * 36];   // [qrow][key] pad 36

    int tid = threadIdx.x;
    int lane = tid & 31, wid = tid >> 5;
    int lr = lane >> 2, lc = lane & 3;
    int q0 = blockIdx.x * 64;
    int bh = blockIdx.y;
    int b = bh / H_, h = bh % H_;
    int kvh = h / GQA;

    // Load Q tile (64x64), scale, convert tf32
    #pragma unroll
    for (int i = 0; i < 8; i++) {
        int li = tid + i * 128;
        int r = li >> 4, c4 = li & 15;
        const float* qp = g_q + (((size_t)(b * LJ + q0 + r)) * H_ + h) * HD_ + c4 * 4;
        float4 v = *(const float4*)qp;
        uint32_t* s = &Qs[r * 68 + c4 * 4];
        s[0] = f2tf(v.x * 0.125f); s[1] = f2tf(v.y * 0.125f);
        s[2] = f2tf(v.z * 0.125f); s[3] = f2tf(v.w * 0.125f);
    }

    bool is_exp = (q0 >= LV);
    int kend_blk = is_exp ? LJ : LV;

    float O[8][4];
    #pragma unroll
    for (int nt = 0; nt < 8; nt++)
        #pragma unroll
        for (int i = 0; i < 4; i++) O[nt][i] = 0.f;
    float m0r = -1e30f, m1r = -1e30f;
    float l0r = 0.f,    l1r = 0.f;

    for (int k0 = 0; k0 < kend_blk; k0 += 32) {
        __syncthreads();   // protect Qs (1st iter) / previous tile reads
        // Load K,V tile (32x64 each): 512 float4 each, 4 per thread each
        #pragma unroll
        for (int i = 0; i < 4; i++) {
            int li = tid + i * 128;
            int r = li >> 4, c4 = li & 15;
            size_t off = (((size_t)(b * LJ + k0 + r)) * KVH_ + kvh) * HD_ + c4 * 4;
            float4 kv = *(const float4*)(g_k + off);
            float4 vv = *(const float4*)(g_v + off);
            uint32_t* sk = &Kt[r * 68 + c4 * 4];
            sk[0] = f2tf(kv.x); sk[1] = f2tf(kv.y); sk[2] = f2tf(kv.z); sk[3] = f2tf(kv.w);
            uint32_t* sv = &Vs[r * 72 + c4 * 4];
            sv[0] = f2tf(vv.x); sv[1] = f2tf(vv.y); sv[2] = f2tf(vv.z); sv[3] = f2tf(vv.w);
        }
        __syncthreads();

        // S = Q * K^T  (rows: wid*16 + lr (+8); keys: nt*8 + 2lc (+1))
        float S[4][4];
        #pragma unroll
        for (int nt = 0; nt < 4; nt++)
            #pragma unroll
            for (int i = 0; i < 4; i++) S[nt][i] = 0.f;

        #pragma unroll
        for (int k8 = 0; k8 < 8; k8++) {
            uint32_t a[4];
            int r = wid * 16 + lr;
            int c = k8 * 8 + lc;
            a[0] = Qs[r * 68 + c];
            a[1] = Qs[(r + 8) * 68 + c];
            a[2] = Qs[r * 68 + c + 4];
            a[3] = Qs[(r + 8) * 68 + c + 4];
            #pragma unroll
            for (int nt = 0; nt < 4; nt++) {
                uint32_t bb[2];
                int key = nt * 8 + lr;
                bb[0] = Kt[key * 68 + k8 * 8 + lc];
                bb[1] = Kt[key * 68 + k8 * 8 + lc + 4];
                mma_tf32(S[nt], a, bb);
            }
        }

        // Causal mask (exp block, last two tiles only)
        if (is_exp && k0 + 32 > LV) {
            int qi0 = q0 + wid * 16 + lr;
            #pragma unroll
            for (int nt = 0; nt < 4; nt++) {
                int jg = k0 + nt * 8 + lc * 2;
                if (jg     > qi0)     S[nt][0] = -1e30f;
                if (jg + 1 > qi0)     S[nt][1] = -1e30f;
                if (jg     > qi0 + 8) S[nt][2] = -1e30f;
                if (jg + 1 > qi0 + 8) S[nt][3] = -1e30f;
            }
        }

        // Row max over lane-local + row group (lanes sharing lane>>2)
        float mt0 = -1e30f, mt1 = -1e30f;
        #pragma unroll
        for (int nt = 0; nt < 4; nt++) {
            mt0 = fmaxf(mt0, fmaxf(S[nt][0], S[nt][1]));
            mt1 = fmaxf(mt1, fmaxf(S[nt][2], S[nt][3]));
        }
        mt0 = fmaxf(mt0, __shfl_xor_sync(0xffffffffu, mt0, 1));
        mt0 = fmaxf(mt0, __shfl_xor_sync(0xffffffffu, mt0, 2));
        mt1 = fmaxf(mt1, __shfl_xor_sync(0xffffffffu, mt1, 1));
        mt1 = fmaxf(mt1, __shfl_xor_sync(0xffffffffu, mt1, 2));

        float mn0 = fmaxf(m0r, mt0), mn1 = fmaxf(m1r, mt1);
        float c0 = __expf(m0r - mn0), c1 = __expf(m1r - mn1);
        m0r = mn0; m1r = mn1;

        #pragma unroll
        for (int nt = 0; nt < 8; nt++) {
            O[nt][0] *= c0; O[nt][1] *= c0;
            O[nt][2] *= c1; O[nt][3] *= c1;
        }

        // P = exp(S - m), partial row sums
        float ps0 = 0.f, ps1 = 0.f;
        #pragma unroll
        for (int nt = 0; nt < 4; nt++) {
            S[nt][0] = __expf(S[nt][0] - mn0);
            S[nt][1] = __expf(S[nt][1] - mn0);
            S[nt][2] = __expf(S[nt][2] - mn1);
            S[nt][3] = __expf(S[nt][3] - mn1);
            ps0 += S[nt][0] + S[nt][1];
            ps1 += S[nt][2] + S[nt][3];
        }
        ps0 += __shfl_xor_sync(0xffffffffu, ps0, 1);
        ps0 += __shfl_xor_sync(0xffffffffu, ps0, 2);
        ps1 += __shfl_xor_sync(0xffffffffu, ps1, 1);
        ps1 += __shfl_xor_sync(0xffffffffu, ps1, 2);
        l0r = l0r * c0 + ps0;
        l1r = l1r * c1 + ps1;

        // P -> smem (tf32), own 16-row region
        {
            int r = wid * 16 + lr;
            #pragma unroll
            for (int nt = 0; nt < 4; nt++) {
                int kc = nt * 8 + lc * 2;
                Ps[r * 36 + kc]           = f2tf(S[nt][0]);
                Ps[r * 36 + kc + 1]       = f2tf(S[nt][1]);
                Ps[(r + 8) * 36 + kc]     = f2tf(S[nt][2]);
                Ps[(r + 8) * 36 + kc + 1] = f2tf(S[nt][3]);
            }
        }
        __syncwarp();

        // O += P * V   (A = P(16x32), B = V(32x64))
        #pragma unroll
        for (int k8 = 0; k8 < 4; k8++) {
            uint32_t a[4];
            int r = wid * 16 + lr;
            int c = k8 * 8 + lc;
            a[0] = Ps[r * 36 + c];
            a[1] = Ps[(r + 8) * 36 + c];
            a[2] = Ps[r * 36 + c + 4];
            a[3] = Ps[(r + 8) * 36 + c + 4];
            #pragma unroll
            for (int nt = 0; nt < 8; nt++) {
                uint32_t bb[2];
                bb[0] = Vs[(k8 * 8 + lc) * 72 + nt * 8 + lr];
                bb[1] = Vs[(k8 * 8 + lc + 4) * 72 + nt * 8 + lr];
                mma_tf32(O[nt], a, bb);
            }
        }
        __syncwarp();   // Ps reads done before next tile's writes
    }

    // Epilogue: O /= l, write g_attn
    float inv0 = 1.f / l0r, inv1 = 1.f / l1r;
    int qi0 = q0 + wid * 16 + lr;
    float* op0 = g_attn + ((size_t)(b * LJ + qi0)) * (H_ * HD_) + h * HD_;
    float* op1 = g_attn + ((size_t)(b * LJ + qi0 + 8)) * (H_ * HD_) + h * HD_;
    #pragma unroll
    for (int nt = 0; nt < 8; nt++) {
        int col = nt * 8 + lc * 2;
        float2 o0; o0.x = O[nt][0] * inv0; o0.y = O[nt][1] * inv0;
        float2 o1; o1.x = O[nt][2] * inv1; o1.y = O[nt][3] * inv1;
        *(float2*)(op0 + col) = o0;
        *(float2*)(op1 + col) = o1;
    }
}

// -------------------------------------------------------------------------
// Launch
// -------------------------------------------------------------------------
extern "C" void kernel_launch(void* const* d_in, const int* in_sizes, int n_in,
                              void* d_out, int out_size)
{
    const float* h_v  = (const float*)d_in[0];
    const float* h_e  = (const float*)d_in[1];
    const float* ln_v = (const float*)d_in[2];
    const float* wq_v = (const float*)d_in[3];
    const float* wk_v = (const float*)d_in[4];
    const float* wv_v = (const float*)d_in[5];
    const float* wo_v = (const float*)d_in[6];
    const float* ln_e = (const float*)d_in[7];
    const float* wq_e = (const float*)d_in[8];
    const float* wk_e = (const float*)d_in[9];
    const float* wv_e = (const float*)d_in[10];
    const float* wo_e = (const float*)d_in[11];
    const int*  pos_v = (const int*)d_in[12];
    const int*  pos_e = (const int*)d_in[13];
    float* out = (float*)d_out;

    float *xn, *q, *k, *v, *attn;
    cudaGetSymbolAddress((void**)&xn,   g_xn);
    cudaGetSymbolAddress((void**)&q,    g_q);
    cudaGetSymbolAddress((void**)&k,    g_k);
    cudaGetSymbolAddress((void**)&v,    g_v);
    cudaGetSymbolAddress((void**)&attn, g_attn);

    // 1) RMSNorm into joint-layout xn
    rmsnorm_kernel<<<B_ * LV, 256>>>(h_v, ln_v, xn, LV, 0);
    rmsnorm_kernel<<<B_ * LE, 256>>>(h_e, ln_e, xn, LE, LV);

    // 2) QKV GEMMs (tf32 tensor cores)
    dim3 gqv(64, 15), gkv(64, 5), gqe(2, 15), gke(2, 5);
    gemm_tc<<<gqv, 256>>>(xn, wq_v, q, LV, 0,  D_, 960, 960, nullptr, 0, D_);
    gemm_tc<<<gkv, 256>>>(xn, wk_v, k, LV, 0,  D_, 320, 320, nullptr, 0, D_);
    gemm_tc<<<gkv, 256>>>(xn, wv_v, v, LV, 0,  D_, 320, 320, nullptr, 0, D_);
    gemm_tc<<<gqe, 256>>>(xn, wq_e, q, LE, LV, D_, 960, 960, nullptr, 0, D_);
    gemm_tc<<<gke, 256>>>(xn, wk_e, k, LE, LV, D_, 320, 320, nullptr, 0, D_);
    gemm_tc<<<gke, 256>>>(xn, wv_e, v, LE, LV, D_, 320, 320, nullptr, 0, D_);

    // 3) RoPE in-place on q, k
    {
        const int total = B_ * LJ * (H_ + KVH_) * (HD_ / 2);
        rope_kernel<<<(total + 255) / 256, 256>>>(pos_v, pos_e);
    }

    // 4) Attention (tf32 tensor cores)
    {
        dim3 grid(LJ / 64, B_ * H_);   // 33 x 60
        attn_tc<<<grid, 128>>>();
    }

    // 5) Output projection + residual into d_out
    gemm_tc<<<gqv, 256>>>(attn, wo_v, out, LV, 0,  960, 960, 960, h_v, 960, 960);
    gemm_tc<<<gqe, 256>>>(attn, wo_e, out, LE, LV, 960, 960, 960, h_e, 960, 960);
}

// round 5
// speedup vs baseline: 5.3453x; 1.1500x over previous
#include <cuda_runtime.h>
#include <math.h>
#include <stdint.h>

// Problem constants
#define B_   4
#define LV   2048
#define LE   64
#define LJ   2112     // Lv + Le
#define D_   960
#define H_   15
#define KVH_ 5
#define HD_  64
#define GQA  3        // H / KVH

// Scratch (device globals: no allocation allowed)
__device__ __align__(16) float g_xn  [B_ * LJ * D_];
__device__ __align__(16) float g_q   [B_ * LJ * H_  * HD_];
__device__ __align__(16) float g_k   [B_ * LJ * KVH_* HD_];
__device__ __align__(16) float g_v   [B_ * LJ * KVH_* HD_];
__device__ __align__(16) float g_attn[B_ * LJ * H_  * HD_];

// -------------------------------------------------------------------------
// helpers
// -------------------------------------------------------------------------
__device__ __forceinline__ uint32_t f2tf(float f) {
    uint32_t u;
    asm("cvt.rna.tf32.f32 %0, %1;" : "=r"(u) : "f"(f));
    return u;
}

__device__ __forceinline__ void mma_tf32(float d[4], const uint32_t a[4], const uint32_t b[2]) {
    asm volatile(
        "mma.sync.aligned.m16n8k8.row.col.f32.tf32.tf32.f32 "
        "{%0,%1,%2,%3}, {%4,%5,%6,%7}, {%8,%9}, {%0,%1,%2,%3};"
        : "+f"(d[0]), "+f"(d[1]), "+f"(d[2]), "+f"(d[3])
        : "r"(a[0]), "r"(a[1]), "r"(a[2]), "r"(a[3]), "r"(b[0]), "r"(b[1]));
}

__device__ __forceinline__ void cp16(uint32_t dst_smem, const void* src) {
    asm volatile("cp.async.cg.shared.global [%0], [%1], 16;" :: "r"(dst_smem), "l"(src));
}
#define CP_COMMIT() asm volatile("cp.async.commit_group;")
#define CP_WAIT1()  asm volatile("cp.async.wait_group 1;")
#define CP_WAIT0()  asm volatile("cp.async.wait_group 0;")

// -------------------------------------------------------------------------
// RMSNorm
// -------------------------------------------------------------------------
__global__ void rmsnorm_kernel(const float* __restrict__ h, const float* __restrict__ w,
                               float* __restrict__ out, int Lseg, int offset)
{
    int m = blockIdx.x;
    int b = m / Lseg, r = m % Lseg;
    const float* x = h + (size_t)m * D_;
    float* y = out + ((size_t)(b * LJ + offset + r)) * D_;

    float ss = 0.f;
    for (int i = threadIdx.x; i < D_; i += blockDim.x) { float t = x[i]; ss += t * t; }

    __shared__ float red[32];
    for (int o = 16; o; o >>= 1) ss += __shfl_down_sync(0xffffffffu, ss, o);
    if ((threadIdx.x & 31) == 0) red[threadIdx.x >> 5] = ss;
    __syncthreads();
    if (threadIdx.x < 32) {
        float v2 = (threadIdx.x < (blockDim.x >> 5)) ? red[threadIdx.x] : 0.f;
        for (int o = 16; o; o >>= 1) v2 += __shfl_down_sync(0xffffffffu, v2, o);
        if (threadIdx.x == 0) red[0] = rsqrtf(v2 / (float)D_ + 1e-6f);
    }
    __syncthreads();
    float rs = red[0];
    for (int i = threadIdx.x; i < D_; i += blockDim.x) y[i] = x[i] * rs * w[i];
}

// -------------------------------------------------------------------------
// tf32 tensor-core GEMM, cp.async double-buffered.
// C[map(m), n] = A[map(m), :] * W[:, n] (+residual[m,n])
// BM=128, BN=64, BK=32; 8 warps (4Mx2N), warp 32x32.
// Smem holds raw fp32 (HMMA tf32 reads top bits; cutlass fast path).
// Pads: As stride 36, Bs stride 72 -> conflict-free fragment LDS.
// -------------------------------------------------------------------------
__global__ __launch_bounds__(256)
void gemm_tc(const float* __restrict__ A, const float* __restrict__ W,
             float* __restrict__ C,
             int Lseg, int offset, int lda, int ldw, int ldc,
             const float* __restrict__ residual, int ldres, int K)
{
    __shared__ float As[2][128 * 36];
    __shared__ float Bs[2][32 * 72];

    int tid = threadIdx.x;
    int lane = tid & 31, wid = tid >> 5;
    int wm = wid & 3;
    int wn = wid >> 2;
    int lr = lane >> 2, lc = lane & 3;
    int row0 = blockIdx.x * 128;
    int col0 = blockIdx.y * 64;

    // Per-thread load coordinates (fixed across tiles)
    int ar[4], ac4[4]; const float* asrc[4];
    #pragma unroll
    for (int i = 0; i < 4; i++) {
        int li = tid + i * 256;
        ar[i] = li >> 3; ac4[i] = li & 7;
        int gr = row0 + ar[i];
        int arow = (gr / Lseg) * LJ + offset + (gr % Lseg);
        asrc[i] = A + (size_t)arow * lda + ac4[i] * 4;
    }
    int br[2], bc4[2]; const float* bsrc[2];
    #pragma unroll
    for (int i = 0; i < 2; i++) {
        int li = tid + i * 256;
        br[i] = li >> 4; bc4[i] = li & 15;
        bsrc[i] = W + (size_t)br[i] * ldw + col0 + bc4[i] * 4;
    }

    uint32_t asb = (uint32_t)__cvta_generic_to_shared(&As[0][0]);
    uint32_t bsb = (uint32_t)__cvta_generic_to_shared(&Bs[0][0]);

    auto load_tile = [&](int k0, int buf) {
        #pragma unroll
        for (int i = 0; i < 4; i++)
            cp16(asb + (buf * 128 * 36 + ar[i] * 36 + ac4[i] * 4) * 4, asrc[i] + k0);
        #pragma unroll
        for (int i = 0; i < 2; i++)
            cp16(bsb + (buf * 32 * 72 + br[i] * 72 + bc4[i] * 4) * 4, bsrc[i] + (size_t)k0 * ldw);
        CP_COMMIT();
    };

    float acc[2][4][4];
    #pragma unroll
    for (int mt = 0; mt < 2; mt++)
        #pragma unroll
        for (int nt = 0; nt < 4; nt++)
            #pragma unroll
            for (int i = 0; i < 4; i++) acc[mt][nt][i] = 0.f;

    int ntiles = K >> 5;
    load_tile(0, 0);

    for (int t = 0; t < ntiles; t++) {
        if (t + 1 < ntiles) { load_tile((t + 1) << 5, (t + 1) & 1); CP_WAIT1(); }
        else CP_WAIT0();
        __syncthreads();

        const float* Ab = As[t & 1];
        const float* Bb = Bs[t & 1];
        #pragma unroll
        for (int k8 = 0; k8 < 4; k8++) {
            uint32_t a[2][4], b[4][2];
            #pragma unroll
            for (int mt = 0; mt < 2; mt++) {
                int r = wm * 32 + mt * 16 + lr;
                int c = k8 * 8 + lc;
                a[mt][0] = __float_as_uint(Ab[r * 36 + c]);
                a[mt][1] = __float_as_uint(Ab[(r + 8) * 36 + c]);
                a[mt][2] = __float_as_uint(Ab[r * 36 + c + 4]);
                a[mt][3] = __float_as_uint(Ab[(r + 8) * 36 + c + 4]);
            }
            #pragma unroll
            for (int nt = 0; nt < 4; nt++) {
                int n = wn * 32 + nt * 8 + lr;
                int kk = k8 * 8 + lc;
                b[nt][0] = __float_as_uint(Bb[kk * 72 + n]);
                b[nt][1] = __float_as_uint(Bb[(kk + 4) * 72 + n]);
            }
            #pragma unroll
            for (int mt = 0; mt < 2; mt++)
                #pragma unroll
                for (int nt = 0; nt < 4; nt++)
                    mma_tf32(acc[mt][nt], a[mt], b[nt]);
        }
        __syncthreads();
    }

    #pragma unroll
    for (int mt = 0; mt < 2; mt++) {
        int m0 = row0 + wm * 32 + mt * 16 + lr;
        #pragma unroll
        for (int hh = 0; hh < 2; hh++) {
            int gm = m0 + hh * 8;
            int cm = (gm / Lseg) * LJ + offset + (gm % Lseg);
            #pragma unroll
            for (int nt = 0; nt < 4; nt++) {
                int gc = col0 + wn * 32 + nt * 8 + lc * 2;
                float v0 = acc[mt][nt][hh * 2 + 0];
                float v1 = acc[mt][nt][hh * 2 + 1];
                if (residual) {
                    v0 += residual[(size_t)gm * ldres + gc];
                    v1 += residual[(size_t)gm * ldres + gc + 1];
                }
                float2 o; o.x = v0; o.y = v1;
                *(float2*)(C + (size_t)cm * ldc + gc) = o;
            }
        }
    }
}

// -------------------------------------------------------------------------
// RoPE
// -------------------------------------------------------------------------
__global__ void rope_kernel(const int* __restrict__ pos_v, const int* __restrict__ pos_e)
{
    const int total = B_ * LJ * (H_ + KVH_) * (HD_ / 2);
    int idx = blockIdx.x * blockDim.x + threadIdx.x;
    if (idx >= total) return;
    int dh   = idx & 31;
    int t    = idx >> 5;
    int head = t % (H_ + KVH_);
    int tok  = t / (H_ + KVH_);
    int b = tok / LJ, i = tok % LJ;

    int p = (i < LV) ? pos_v[b * LV + i] : pos_e[b * LE + (i - LV)];
    float ts  = powf(10000.0f, (float)dh * (2.0f / 64.0f));
    float rad = (float)p / ts;
    float sn, cs;
    sincosf(rad, &sn, &cs);

    float* base;
    if (head < H_) base = g_q + (((size_t)(b * LJ + i)) * H_   + head)        * HD_;
    else           base = g_k + (((size_t)(b * LJ + i)) * KVH_ + (head - H_)) * HD_;

    float x1 = base[dh], x2 = base[dh + 32];
    base[dh]      = x1 * cs - x2 * sn;
    base[dh + 32] = x2 * cs + x1 * sn;
}

// -------------------------------------------------------------------------
// Tensor-core flash attention, cp.async double-buffered K/V tiles.
// One CTA = one (b,h) x 64 queries; 4 warps x 16 rows; key tile 32.
// K/V smem holds raw fp32 (tf32 truncation at mma). Q/P keep rna cvt.
// -------------------------------------------------------------------------
__global__ __launch_bounds__(128)
void attn_tc()
{
    __shared__ uint32_t Qs[64 * 68];
    __shared__ float    Kt[2][32 * 68];
    __shared__ float    Vs[2][32 * 72];
    __shared__ uint32_t Ps[64 * 36];

    int tid = threadIdx.x;
    int lane = tid & 31, wid = tid >> 5;
    int lr = lane >> 2, lc = lane & 3;
    int q0 = blockIdx.x * 64;
    int bh = blockIdx.y;
    int b = bh / H_, h = bh % H_;
    int kvh = h / GQA;

    // Load Q tile (64x64), scale, rna->tf32
    #pragma unroll
    for (int i = 0; i < 8; i++) {
        int li = tid + i * 128;
        int r = li >> 4, c4 = li & 15;
        const float* qp = g_q + (((size_t)(b * LJ + q0 + r)) * H_ + h) * HD_ + c4 * 4;
        float4 v = *(const float4*)qp;
        uint32_t* s = &Qs[r * 68 + c4 * 4];
        s[0] = f2tf(v.x * 0.125f); s[1] = f2tf(v.y * 0.125f);
        s[2] = f2tf(v.z * 0.125f); s[3] = f2tf(v.w * 0.125f);
    }

    bool is_exp = (q0 >= LV);
    int ntiles = (is_exp ? LJ : LV) >> 5;

    // K/V load coordinates (4 cp.async each per thread)
    int kr[4], kc4[4];
    #pragma unroll
    for (int i = 0; i < 4; i++) { int li = tid + i * 128; kr[i] = li >> 4; kc4[i] = li & 15; }
    uint32_t ktb = (uint32_t)__cvta_generic_to_shared(&Kt[0][0]);
    uint32_t vsb = (uint32_t)__cvta_generic_to_shared(&Vs[0][0]);

    auto load_kv = [&](int k0, int buf) {
        #pragma unroll
        for (int i = 0; i < 4; i++) {
            size_t off = (((size_t)(b * LJ + k0 + kr[i])) * KVH_ + kvh) * HD_ + kc4[i] * 4;
            cp16(ktb + (buf * 32 * 68 + kr[i] * 68 + kc4[i] * 4) * 4, g_k + off);
            cp16(vsb + (buf * 32 * 72 + kr[i] * 72 + kc4[i] * 4) * 4, g_v + off);
        }
        CP_COMMIT();
    };

    float O[8][4];
    #pragma unroll
    for (int nt = 0; nt < 8; nt++)
        #pragma unroll
        for (int i = 0; i < 4; i++) O[nt][i] = 0.f;
    float m0r = -1e30f, m1r = -1e30f;
    float l0r = 0.f,    l1r = 0.f;

    load_kv(0, 0);

    for (int t = 0; t < ntiles; t++) {
        int k0 = t << 5;
        if (t + 1 < ntiles) { load_kv((t + 1) << 5, (t + 1) & 1); CP_WAIT1(); }
        else CP_WAIT0();
        __syncthreads();

        const float* Kb = Kt[t & 1];
        const float* Vb = Vs[t & 1];

        // S = Q * K^T
        float S[4][4];
        #pragma unroll
        for (int nt = 0; nt < 4; nt++)
            #pragma unroll
            for (int i = 0; i < 4; i++) S[nt][i] = 0.f;

        #pragma unroll
        for (int k8 = 0; k8 < 8; k8++) {
            uint32_t a[4];
            int r = wid * 16 + lr;
            int c = k8 * 8 + lc;
            a[0] = Qs[r * 68 + c];
            a[1] = Qs[(r + 8) * 68 + c];
            a[2] = Qs[r * 68 + c + 4];
            a[3] = Qs[(r + 8) * 68 + c + 4];
            #pragma unroll
            for (int nt = 0; nt < 4; nt++) {
                uint32_t bb[2];
                int key = nt * 8 + lr;
                bb[0] = __float_as_uint(Kb[key * 68 + k8 * 8 + lc]);
                bb[1] = __float_as_uint(Kb[key * 68 + k8 * 8 + lc + 4]);
                mma_tf32(S[nt], a, bb);
            }
        }

        // Causal mask (exp block, last two tiles only)
        if (is_exp && k0 + 32 > LV) {
            int qi0 = q0 + wid * 16 + lr;
            #pragma unroll
            for (int nt = 0; nt < 4; nt++) {
                int jg = k0 + nt * 8 + lc * 2;
                if (jg     > qi0)     S[nt][0] = -1e30f;
                if (jg + 1 > qi0)     S[nt][1] = -1e30f;
                if (jg     > qi0 + 8) S[nt][2] = -1e30f;
                if (jg + 1 > qi0 + 8) S[nt][3] = -1e30f;
            }
        }

        // Online softmax
        float mt0 = -1e30f, mt1 = -1e30f;
        #pragma unroll
        for (int nt = 0; nt < 4; nt++) {
            mt0 = fmaxf(mt0, fmaxf(S[nt][0], S[nt][1]));
            mt1 = fmaxf(mt1, fmaxf(S[nt][2], S[nt][3]));
        }
        mt0 = fmaxf(mt0, __shfl_xor_sync(0xffffffffu, mt0, 1));
        mt0 = fmaxf(mt0, __shfl_xor_sync(0xffffffffu, mt0, 2));
        mt1 = fmaxf(mt1, __shfl_xor_sync(0xffffffffu, mt1, 1));
        mt1 = fmaxf(mt1, __shfl_xor_sync(0xffffffffu, mt1, 2));

        float mn0 = fmaxf(m0r, mt0), mn1 = fmaxf(m1r, mt1);
        float c0 = __expf(m0r - mn0), c1 = __expf(m1r - mn1);
        m0r = mn0; m1r = mn1;

        #pragma unroll
        for (int nt = 0; nt < 8; nt++) {
            O[nt][0] *= c0; O[nt][1] *= c0;
            O[nt][2] *= c1; O[nt][3] *= c1;
        }

        float ps0 = 0.f, ps1 = 0.f;
        #pragma unroll
        for (int nt = 0; nt < 4; nt++) {
            S[nt][0] = __expf(S[nt][0] - mn0);
            S[nt][1] = __expf(S[nt][1] - mn0);
            S[nt][2] = __expf(S[nt][2] - mn1);
            S[nt][3] = __expf(S[nt][3] - mn1);
            ps0 += S[nt][0] + S[nt][1];
            ps1 += S[nt][2] + S[nt][3];
        }
        ps0 += __shfl_xor_sync(0xffffffffu, ps0, 1);
        ps0 += __shfl_xor_sync(0xffffffffu, ps0, 2);
        ps1 += __shfl_xor_sync(0xffffffffu, ps1, 1);
        ps1 += __shfl_xor_sync(0xffffffffu, ps1, 2);
        l0r = l0r * c0 + ps0;
        l1r = l1r * c1 + ps1;

        // P -> smem (tf32), own 16-row region
        {
            int r = wid * 16 + lr;
            #pragma unroll
            for (int nt = 0; nt < 4; nt++) {
                int kc = nt * 8 + lc * 2;
                Ps[r * 36 + kc]           = f2tf(S[nt][0]);
                Ps[r * 36 + kc + 1]       = f2tf(S[nt][1]);
                Ps[(r + 8) * 36 + kc]     = f2tf(S[nt][2]);
                Ps[(r + 8) * 36 + kc + 1] = f2tf(S[nt][3]);
            }
        }
        __syncwarp();

        // O += P * V
        #pragma unroll
        for (int k8 = 0; k8 < 4; k8++) {
            uint32_t a[4];
            int r = wid * 16 + lr;
            int c = k8 * 8 + lc;
            a[0] = Ps[r * 36 + c];
            a[1] = Ps[(r + 8) * 36 + c];
            a[2] = Ps[r * 36 + c + 4];
            a[3] = Ps[(r + 8) * 36 + c + 4];
            #pragma unroll
            for (int nt = 0; nt < 8; nt++) {
                uint32_t bb[2];
                bb[0] = __float_as_uint(Vb[(k8 * 8 + lc) * 72 + nt * 8 + lr]);
                bb[1] = __float_as_uint(Vb[(k8 * 8 + lc + 4) * 72 + nt * 8 + lr]);
                mma_tf32(O[nt], a, bb);
            }
        }
        __syncthreads();   // all warps done reading buf before next cp.async overwrites
    }

    // Epilogue
    float inv0 = 1.f / l0r, inv1 = 1.f / l1r;
    int qi0 = q0 + wid * 16 + lr;
    float* op0 = g_attn + ((size_t)(b * LJ + qi0)) * (H_ * HD_) + h * HD_;
    float* op1 = g_attn + ((size_t)(b * LJ + qi0 + 8)) * (H_ * HD_) + h * HD_;
    #pragma unroll
    for (int nt = 0; nt < 8; nt++) {
        int col = nt * 8 + lc * 2;
        float2 o0; o0.x = O[nt][0] * inv0; o0.y = O[nt][1] * inv0;
        float2 o1; o1.x = O[nt][2] * inv1; o1.y = O[nt][3] * inv1;
        *(float2*)(op0 + col) = o0;
        *(float2*)(op1 + col) = o1;
    }
}

// -------------------------------------------------------------------------
// Launch
// -------------------------------------------------------------------------
extern "C" void kernel_launch(void* const* d_in, const int* in_sizes, int n_in,
                              void* d_out, int out_size)
{
    const float* h_v  = (const float*)d_in[0];
    const float* h_e  = (const float*)d_in[1];
    const float* ln_v = (const float*)d_in[2];
    const float* wq_v = (const float*)d_in[3];
    const float* wk_v = (const float*)d_in[4];
    const float* wv_v = (const float*)d_in[5];
    const float* wo_v = (const float*)d_in[6];
    const float* ln_e = (const float*)d_in[7];
    const float* wq_e = (const float*)d_in[8];
    const float* wk_e = (const float*)d_in[9];
    const float* wv_e = (const float*)d_in[10];
    const float* wo_e = (const float*)d_in[11];
    const int*  pos_v = (const int*)d_in[12];
    const int*  pos_e = (const int*)d_in[13];
    float* out = (float*)d_out;

    float *xn, *q, *k, *v, *attn;
    cudaGetSymbolAddress((void**)&xn,   g_xn);
    cudaGetSymbolAddress((void**)&q,    g_q);
    cudaGetSymbolAddress((void**)&k,    g_k);
    cudaGetSymbolAddress((void**)&v,    g_v);
    cudaGetSymbolAddress((void**)&attn, g_attn);

    // 1) RMSNorm into joint-layout xn
    rmsnorm_kernel<<<B_ * LV, 256>>>(h_v, ln_v, xn, LV, 0);
    rmsnorm_kernel<<<B_ * LE, 256>>>(h_e, ln_e, xn, LE, LV);

    // 2) QKV GEMMs (tf32 tensor cores, pipelined)
    dim3 gqv(64, 15), gkv(64, 5), gqe(2, 15), gke(2, 5);
    gemm_tc<<<gqv, 256>>>(xn, wq_v, q, LV, 0,  D_, 960, 960, nullptr, 0, D_);
    gemm_tc<<<gkv, 256>>>(xn, wk_v, k, LV, 0,  D_, 320, 320, nullptr, 0, D_);
    gemm_tc<<<gkv, 256>>>(xn, wv_v, v, LV, 0,  D_, 320, 320, nullptr, 0, D_);
    gemm_tc<<<gqe, 256>>>(xn, wq_e, q, LE, LV, D_, 960, 960, nullptr, 0, D_);
    gemm_tc<<<gke, 256>>>(xn, wk_e, k, LE, LV, D_, 320, 320, nullptr, 0, D_);
    gemm_tc<<<gke, 256>>>(xn, wv_e, v, LE, LV, D_, 320, 320, nullptr, 0, D_);

    // 3) RoPE in-place on q, k
    {
        const int total = B_ * LJ * (H_ + KVH_) * (HD_ / 2);
        rope_kernel<<<(total + 255) / 256, 256>>>(pos_v, pos_e);
    }

    // 4) Attention (tf32 tensor cores, pipelined)
    {
        dim3 grid(LJ / 64, B_ * H_);   // 33 x 60
        attn_tc<<<grid, 128>>>();
    }

    // 5) Output projection + residual into d_out
    gemm_tc<<<gqv, 256>>>(attn, wo_v, out, LV, 0,  960, 960, 960, h_v, 960, 960);
    gemm_tc<<<gqe, 256>>>(attn, wo_e, out, LE, LV, 960, 960, 960, h_e, 960, 960);
}